// round 12
// baseline (speedup 1.0000x reference)
#include <cuda_runtime.h>
#include <math.h>
#include <cstdint>

#define NN 1024
#define FF 128
#define H0C 192
#define H1C 96
#define THREADS 768
#define GRIDX 148
#define TILES_SYM 4608       // sum over ib of 128*(8-ib)

// ---------------- SMEM layout (bytes) ----------------
#define SM_W0F   0           // 12 qg * 8 kt * 32 * 16B = 49152
#define SM_W1F   49152       // 6 qg * 12 kt * 32 * 16B = 36864
#define SM_XF    86016       // 8 mt * 8 kt frags, 33-uint4 stride = 33792
#define SM_HF    119808      // 8 mt * 12 kt * 32 * 16B = 49152
#define SM_BN0   168960      // 192 floats
#define SM_BN1   169728      // 96 floats
#define SM_WOUT  170112      // 96 floats
#define SM_RED   170496      // 6*128 floats = 3072
#define SM_BOUT  173568
#define SMEM_BYTES 173584

__device__ __forceinline__ uint32_t pack_bf16x2(float lo, float hi) {
    uint32_t r;
    asm("cvt.rn.bf16x2.f32 %0, %1, %2;" : "=r"(r) : "f"(hi), "f"(lo));
    return r;
}
__device__ __forceinline__ float leaky(float x) {
    return fmaxf(x, 0.0f) + 0.01f * fminf(x, 0.0f);
}
__device__ __forceinline__ void mma_bf16(float* d, const uint32_t* a,
                                         uint32_t b0, uint32_t b1) {
    asm volatile(
        "mma.sync.aligned.m16n8k16.row.col.f32.bf16.bf16.f32 "
        "{%0,%1,%2,%3}, {%4,%5,%6,%7}, {%8,%9}, {%0,%1,%2,%3};"
        : "+f"(d[0]), "+f"(d[1]), "+f"(d[2]), "+f"(d[3])
        : "r"(a[0]), "r"(a[1]), "r"(a[2]), "r"(a[3]), "r"(b0), "r"(b1));
}
// group-scoped named barrier: 6 warps (192 threads) of wm-group
__device__ __forceinline__ void group_bar(int wm) {
    asm volatile("bar.sync %0, %1;" :: "r"(1 + wm), "r"(192) : "memory");
}

__global__ void __launch_bounds__(THREADS, 1) edgenet_bf16_kernel(
    const float* __restrict__ feat,
    const float* __restrict__ W0, const float* __restrict__ g0,
    const float* __restrict__ b0, const float* __restrict__ m0,
    const float* __restrict__ v0,
    const float* __restrict__ W1, const float* __restrict__ g1,
    const float* __restrict__ b1, const float* __restrict__ m1,
    const float* __restrict__ v1,
    const float* __restrict__ Wout, const float* __restrict__ bout,
    float* __restrict__ sim_out)
{
    extern __shared__ char smem[];
    uint4*    W0F4 = (uint4*)(smem + SM_W0F);
    uint4*    W1F4 = (uint4*)(smem + SM_W1F);
    uint4*    XF4  = (uint4*)(smem + SM_XF);
    uint32_t* Xw   = (uint32_t*)(smem + SM_XF);
    uint4*    HF4  = (uint4*)(smem + SM_HF);
    float*    bn0S = (float*)(smem + SM_BN0);
    float*    bn1S = (float*)(smem + SM_BN1);
    float*    woutS= (float*)(smem + SM_WOUT);
    float*    redS = (float*)(smem + SM_RED);
    float*    boutS= (float*)(smem + SM_BOUT);

    const int tid  = threadIdx.x;
    const int wid  = tid >> 5;
    const int lane = tid & 31;
    const int g    = lane >> 2;
    const int t4   = lane & 3;

    // ---- stage weights ONCE as bf16 B-fragments (BN scale folded) ----
    for (int idx = tid; idx < 12 * 8 * 32; idx += THREADS) {
        int qg = idx >> 8, kt = (idx >> 5) & 7, ln = idx & 31;
        int c0 = qg * 16 + (ln >> 2);
        int c1 = c0 + 8;
        int f  = kt * 16 + (ln & 3) * 2;
        float s0 = g0[c0] * rsqrtf(v0[c0] + 1e-5f);
        float s1 = g0[c1] * rsqrtf(v0[c1] + 1e-5f);
        uint4 b;
        b.x = pack_bf16x2(W0[c0 * FF + f] * s0,     W0[c0 * FF + f + 1] * s0);
        b.y = pack_bf16x2(W0[c0 * FF + f + 8] * s0, W0[c0 * FF + f + 9] * s0);
        b.z = pack_bf16x2(W0[c1 * FF + f] * s1,     W0[c1 * FF + f + 1] * s1);
        b.w = pack_bf16x2(W0[c1 * FF + f + 8] * s1, W0[c1 * FF + f + 9] * s1);
        W0F4[idx] = b;
    }
    for (int idx = tid; idx < 6 * 12 * 32; idx += THREADS) {
        int qg = idx / 384, kt = (idx / 32) % 12, ln = idx & 31;
        int d0 = qg * 16 + (ln >> 2);
        int d1 = d0 + 8;
        int k  = kt * 16 + (ln & 3) * 2;
        float s0 = g1[d0] * rsqrtf(v1[d0] + 1e-5f);
        float s1 = g1[d1] * rsqrtf(v1[d1] + 1e-5f);
        uint4 b;
        b.x = pack_bf16x2(W1[d0 * H0C + k] * s0,     W1[d0 * H0C + k + 1] * s0);
        b.y = pack_bf16x2(W1[d0 * H0C + k + 8] * s0, W1[d0 * H0C + k + 9] * s0);
        b.z = pack_bf16x2(W1[d1 * H0C + k] * s1,     W1[d1 * H0C + k + 1] * s1);
        b.w = pack_bf16x2(W1[d1 * H0C + k + 8] * s1, W1[d1 * H0C + k + 9] * s1);
        W1F4[idx] = b;
    }
    for (int c = tid; c < H0C; c += THREADS) {
        float s = g0[c] * rsqrtf(v0[c] + 1e-5f);
        bn0S[c] = b0[c] - m0[c] * s;
    }
    for (int d = tid; d < H1C; d += THREADS) {
        float s = g1[d] * rsqrtf(v1[d] + 1e-5f);
        bn1S[d] = b1[d] - m1[d] * s;
        woutS[d] = Wout[d];
    }
    if (tid == 0) boutS[0] = bout[0];
    __syncthreads();
    const float boutv = boutS[0];

    // warp roles: 4 m-groups (wm) x 6 n-groups (wn)
    const int wm = wid & 3;
    const int wn = wid >> 2;

    // buildX constants
    const int bx_kt  = lane >> 2;
    const int bx_pl0 = (2 * lane) & 7;
    const int bx_w0  = (bx_pl0 & 3) * 4;
    const int bx_ph0 = (bx_pl0 >> 2) * 2;
    const int bx_w1  = ((bx_pl0 + 1) & 3) * 4;
    const int bx_ph1 = ((bx_pl0 + 1) >> 2) * 2;

    for (int t = blockIdx.x; t < TILES_SYM; t += GRIDX) {
        // ---- map t -> (i, jb) over the upper-triangle tile set ----
        int ib = (t >= 1024) + (t >= 1920) + (t >= 2688) + (t >= 3328)
               + (t >= 3840) + (t >= 4224) + (t >= 4480);
        int base = 128 * (8 * ib - (ib * (ib - 1)) / 2);
        const int local = t - base;
        const int njb   = 8 - ib;
        const int idiv  = local / njb;
        const int i     = ib * 128 + idiv;
        const int jb    = ib + (local - idiv * njb);

        // ---------- buildX: GROUP-LOCAL rows p = wm*32 + wn + 6*rr ----------
        {
            const float4 fi4 = ((const float4*)(feat + i * FF))[lane];
#pragma unroll
            for (int rr = 0; rr < 6; ++rr) {
                int pl = wn + 6 * rr;
                if (pl < 32) {
                    int p = wm * 32 + pl;
                    float4 fj4 = ((const float4*)(feat + (jb * 128 + p) * FF))[lane];
                    float x0 = fabsf(fi4.x - fj4.x);
                    float x1 = fabsf(fi4.y - fj4.y);
                    float x2 = fabsf(fi4.z - fj4.z);
                    float x3 = fabsf(fi4.w - fj4.w);
                    uint32_t wA = pack_bf16x2(x0, x1);
                    uint32_t wB = pack_bf16x2(x2, x3);
                    int mt = p >> 4, r16 = p & 15;
                    int gg = r16 & 7, rowbit = r16 >> 3;
                    int bidx = ((mt * 8 + bx_kt) * 33 + gg * 4) * 4;
                    Xw[bidx + bx_w0 + bx_ph0 + rowbit] = wA;
                    Xw[bidx + bx_w1 + bx_ph1 + rowbit] = wB;
                }
            }
        }
        group_bar(wm);   // XF[wm rows] built by this group only

        // ---------- GEMM1: [32 rows x 192] slice of X * W0'^T ----------
        float c1r[2][4][4];
#pragma unroll
        for (int mt = 0; mt < 2; ++mt)
#pragma unroll
            for (int nt = 0; nt < 4; ++nt)
#pragma unroll
                for (int r = 0; r < 4; ++r) c1r[mt][nt][r] = 0.0f;

#pragma unroll
        for (int kt = 0; kt < 8; ++kt) {
            uint4 a[2];
#pragma unroll
            for (int mt = 0; mt < 2; ++mt)
                a[mt] = XF4[((wm * 2 + mt) * 8 + kt) * 33 + lane];
#pragma unroll
            for (int q = 0; q < 2; ++q) {
                uint4 b = W0F4[((wn * 2 + q) * 8 + kt) * 32 + lane];
#pragma unroll
                for (int mt = 0; mt < 2; ++mt) {
                    mma_bf16(c1r[mt][q * 2 + 0], (const uint32_t*)&a[mt], b.x, b.y);
                    mma_bf16(c1r[mt][q * 2 + 1], (const uint32_t*)&a[mt], b.z, b.w);
                }
            }
        }

        // ---------- epilogue1: BN shift + leaky -> HF[wm rows] ----------
#pragma unroll
        for (int mt = 0; mt < 2; ++mt) {
            int mtg = wm * 2 + mt;
#pragma unroll
            for (int q = 0; q < 2; ++q) {
                int colA = wn * 32 + q * 16 + 2 * t4;
                int colB = colA + 8;
                float sA0 = bn0S[colA], sA1 = bn0S[colA + 1];
                float sB0 = bn0S[colB], sB1 = bn0S[colB + 1];
                uint4 val;
                val.x = pack_bf16x2(leaky(c1r[mt][q * 2][0] + sA0),
                                    leaky(c1r[mt][q * 2][1] + sA1));
                val.y = pack_bf16x2(leaky(c1r[mt][q * 2][2] + sA0),
                                    leaky(c1r[mt][q * 2][3] + sA1));
                val.z = pack_bf16x2(leaky(c1r[mt][q * 2 + 1][0] + sB0),
                                    leaky(c1r[mt][q * 2 + 1][1] + sB1));
                val.w = pack_bf16x2(leaky(c1r[mt][q * 2 + 1][2] + sB0),
                                    leaky(c1r[mt][q * 2 + 1][3] + sB1));
                HF4[(mtg * 12 + wn * 2 + q) * 32 + lane] = val;
            }
        }
        group_bar(wm);   // HF[wm rows] complete (written by this group only)

        // ---------- GEMM2: [32 rows x 96] = H[wm rows] * W1'^T ----------
        float c2r[2][2][4];
#pragma unroll
        for (int mt = 0; mt < 2; ++mt)
#pragma unroll
            for (int nt = 0; nt < 2; ++nt)
#pragma unroll
                for (int r = 0; r < 4; ++r) c2r[mt][nt][r] = 0.0f;

#pragma unroll
        for (int kt = 0; kt < 12; ++kt) {
            uint4 a[2];
#pragma unroll
            for (int mt = 0; mt < 2; ++mt)
                a[mt] = HF4[((wm * 2 + mt) * 12 + kt) * 32 + lane];
            uint4 b = W1F4[(wn * 12 + kt) * 32 + lane];
#pragma unroll
            for (int mt = 0; mt < 2; ++mt) {
                mma_bf16(c2r[mt][0], (const uint32_t*)&a[mt], b.x, b.y);
                mma_bf16(c2r[mt][1], (const uint32_t*)&a[mt], b.z, b.w);
            }
        }

        // ---------- epilogue2: BN shift + leaky + Wout dot + reduce ----------
#pragma unroll
        for (int mt = 0; mt < 2; ++mt) {
#pragma unroll
            for (int half = 0; half < 2; ++half) {
                float acc = 0.0f;
#pragma unroll
                for (int nt = 0; nt < 2; ++nt) {
                    int col0 = wn * 16 + nt * 8 + 2 * t4;
                    float h0 = leaky(c2r[mt][nt][half * 2 + 0] + bn1S[col0]);
                    float h1 = leaky(c2r[mt][nt][half * 2 + 1] + bn1S[col0 + 1]);
                    acc += woutS[col0] * h0 + woutS[col0 + 1] * h1;
                }
                acc += __shfl_xor_sync(0xffffffffu, acc, 1);
                acc += __shfl_xor_sync(0xffffffffu, acc, 2);
                if (t4 == 0) {
                    int row = (wm * 2 + mt) * 16 + half * 8 + g;
                    redS[wn * 128 + row] = acc;   // row in [wm*32, wm*32+32)
                }
            }
        }
        group_bar(wm);   // redS rows of this wm written only by this group

        // final logit/store: warp `wm` of wn==0 handles rows wm*32..+31
        if (wn == 0) {
            int row = wm * 32 + lane;
            float logit = redS[row] + redS[128 + row] + redS[256 + row]
                        + redS[384 + row] + redS[512 + row] + redS[640 + row]
                        + boutv;
            float s = 1.0f / (1.0f + __expf(-logit));
            int jcol = jb * 128 + row;
            sim_out[i * NN + jcol] = s;
            sim_out[jcol * NN + i] = s;   // symmetric mirror
        }
        // next tile's redS writes by group wm are ordered after this read via
        // this group's next two group_bars (reader warp participates in both)
    }
}

// ---- pass 2: partial column sums of sim over 128-row slabs (float4) ----
__device__ float g_colpart[8][NN];

__global__ void colsum_kernel(const float* __restrict__ sim) {
    int j4 = (blockIdx.x * 256 + threadIdx.x);   // gridDim.x = 1
    int slab = blockIdx.y;
    if (j4 < 256) {
        float4 s = make_float4(0.f, 0.f, 0.f, 0.f);
        int ibase = slab * 128;
#pragma unroll 4
        for (int i = 0; i < 128; ++i) {
            float4 v = ((const float4*)(sim + (ibase + i) * NN))[j4];
            s.x += v.x; s.y += v.y; s.z += v.z; s.w += v.w;
        }
        ((float4*)g_colpart[slab])[j4] = s;
    }
}

// ---- pass 3: edge = (sim + eye + 1e-6) / colsum_over_i (float4) ----
__global__ void edge_kernel(const float* __restrict__ sim, float* __restrict__ edge) {
    int idx4 = blockIdx.x * 256 + threadIdx.x;   // over float4 elements
    int i  = idx4 >> 8;                          // 256 float4 per row
    int j0 = (idx4 & 255) * 4;
    float4 den = make_float4(1.0f + NN * 1e-6f, 1.0f + NN * 1e-6f,
                             1.0f + NN * 1e-6f, 1.0f + NN * 1e-6f);
#pragma unroll
    for (int r = 0; r < 8; ++r) {
        float4 c = ((const float4*)g_colpart[r])[idx4 & 255];
        den.x += c.x; den.y += c.y; den.z += c.z; den.w += c.w;
    }
    float4 v = ((const float4*)sim)[idx4];
    v.x += ((i == j0 + 0) ? 1.0f : 0.0f) + 1e-6f;
    v.y += ((i == j0 + 1) ? 1.0f : 0.0f) + 1e-6f;
    v.z += ((i == j0 + 2) ? 1.0f : 0.0f) + 1e-6f;
    v.w += ((i == j0 + 3) ? 1.0f : 0.0f) + 1e-6f;
    v.x /= den.x; v.y /= den.y; v.z /= den.z; v.w /= den.w;
    ((float4*)edge)[idx4] = v;
}

extern "C" void kernel_launch(void* const* d_in, const int* in_sizes, int n_in,
                              void* d_out, int out_size) {
    const float* feat = (const float*)d_in[0];
    const float* W0   = (const float*)d_in[1];
    const float* g0   = (const float*)d_in[2];
    const float* b0   = (const float*)d_in[3];
    const float* m0   = (const float*)d_in[4];
    const float* v0   = (const float*)d_in[5];
    const float* W1   = (const float*)d_in[6];
    const float* g1   = (const float*)d_in[7];
    const float* b1   = (const float*)d_in[8];
    const float* m1   = (const float*)d_in[9];
    const float* v1   = (const float*)d_in[10];
    const float* Wout = (const float*)d_in[11];
    const float* bout = (const float*)d_in[12];

    float* out  = (float*)d_out;
    float* edge = out;              // edge_feat [1,N,N] first
    float* sim  = out + NN * NN;    // sim_val [N,N] second

    cudaFuncSetAttribute(edgenet_bf16_kernel,
                         cudaFuncAttributeMaxDynamicSharedMemorySize, SMEM_BYTES);

    edgenet_bf16_kernel<<<GRIDX, THREADS, SMEM_BYTES>>>(
        feat, W0, g0, b0, m0, v0, W1, g1, b1, m1, v1, Wout, bout, sim);

    colsum_kernel<<<dim3(1, 8), 256>>>(sim);
    edge_kernel<<<(NN * NN / 4) / 256, 256>>>(sim, edge);
}

// round 13
// speedup vs baseline: 1.0034x; 1.0034x over previous
#include <cuda_runtime.h>
#include <math.h>
#include <cstdint>

#define NN 1024
#define FF 128
#define H0C 192
#define H1C 96
#define THREADS 768
#define GRIDX 148
#define TILES_SYM 4608       // sum over ib of 128*(8-ib)

// ---------------- SMEM layout (bytes) ----------------
#define SM_W0F   0           // 12 qg * 8 kt * 32 * 16B = 49152
#define SM_W1F   49152       // 6 qg * 12 kt * 32 * 16B = 36864
#define SM_XF    86016       // 8 mt * 8 kt frags, 33-uint4 stride = 33792
#define SM_HF    119808      // 8 mt * 12 kt * 32 * 16B = 49152
#define SM_BN0   168960      // 192 floats
#define SM_BN1   169728      // 96 floats
#define SM_WOUT  170112      // 96 floats
#define SM_RED   170496      // 6*128 floats = 3072
#define SM_BOUT  173568
#define SMEM_BYTES 173584

__device__ __forceinline__ uint32_t pack_bf16x2(float lo, float hi) {
    uint32_t r;
    asm("cvt.rn.bf16x2.f32 %0, %1, %2;" : "=r"(r) : "f"(hi), "f"(lo));
    return r;
}
__device__ __forceinline__ float leaky(float x) {
    return fmaxf(x, 0.0f) + 0.01f * fminf(x, 0.0f);
}
__device__ __forceinline__ void mma_bf16(float* d, const uint32_t* a,
                                         uint32_t b0, uint32_t b1) {
    asm volatile(
        "mma.sync.aligned.m16n8k16.row.col.f32.bf16.bf16.f32 "
        "{%0,%1,%2,%3}, {%4,%5,%6,%7}, {%8,%9}, {%0,%1,%2,%3};"
        : "+f"(d[0]), "+f"(d[1]), "+f"(d[2]), "+f"(d[3])
        : "r"(a[0]), "r"(a[1]), "r"(a[2]), "r"(a[3]), "r"(b0), "r"(b1));
}
// group-scoped named barrier: 6 warps (192 threads) of wm-group
__device__ __forceinline__ void group_bar(int wm) {
    asm volatile("bar.sync %0, %1;" :: "r"(1 + wm), "r"(192) : "memory");
}

__global__ void __launch_bounds__(THREADS, 1) edgenet_bf16_kernel(
    const float* __restrict__ feat,
    const float* __restrict__ W0, const float* __restrict__ g0,
    const float* __restrict__ b0, const float* __restrict__ m0,
    const float* __restrict__ v0,
    const float* __restrict__ W1, const float* __restrict__ g1,
    const float* __restrict__ b1, const float* __restrict__ m1,
    const float* __restrict__ v1,
    const float* __restrict__ Wout, const float* __restrict__ bout,
    float* __restrict__ sim_out)
{
    extern __shared__ char smem[];
    uint4*    W0F4 = (uint4*)(smem + SM_W0F);
    uint4*    W1F4 = (uint4*)(smem + SM_W1F);
    uint4*    XF4  = (uint4*)(smem + SM_XF);
    uint32_t* Xw   = (uint32_t*)(smem + SM_XF);
    uint4*    HF4  = (uint4*)(smem + SM_HF);
    float*    bn0S = (float*)(smem + SM_BN0);
    float*    bn1S = (float*)(smem + SM_BN1);
    float*    woutS= (float*)(smem + SM_WOUT);
    float*    redS = (float*)(smem + SM_RED);
    float*    boutS= (float*)(smem + SM_BOUT);

    const int tid  = threadIdx.x;
    const int wid  = tid >> 5;
    const int lane = tid & 31;
    const int g    = lane >> 2;
    const int t4   = lane & 3;

    // ---- stage weights ONCE as bf16 B-fragments (BN scale folded) ----
    for (int idx = tid; idx < 12 * 8 * 32; idx += THREADS) {
        int qg = idx >> 8, kt = (idx >> 5) & 7, ln = idx & 31;
        int c0 = qg * 16 + (ln >> 2);
        int c1 = c0 + 8;
        int f  = kt * 16 + (ln & 3) * 2;
        float s0 = g0[c0] * rsqrtf(v0[c0] + 1e-5f);
        float s1 = g0[c1] * rsqrtf(v0[c1] + 1e-5f);
        uint4 b;
        b.x = pack_bf16x2(W0[c0 * FF + f] * s0,     W0[c0 * FF + f + 1] * s0);
        b.y = pack_bf16x2(W0[c0 * FF + f + 8] * s0, W0[c0 * FF + f + 9] * s0);
        b.z = pack_bf16x2(W0[c1 * FF + f] * s1,     W0[c1 * FF + f + 1] * s1);
        b.w = pack_bf16x2(W0[c1 * FF + f + 8] * s1, W0[c1 * FF + f + 9] * s1);
        W0F4[idx] = b;
    }
    for (int idx = tid; idx < 6 * 12 * 32; idx += THREADS) {
        int qg = idx / 384, kt = (idx / 32) % 12, ln = idx & 31;
        int d0 = qg * 16 + (ln >> 2);
        int d1 = d0 + 8;
        int k  = kt * 16 + (ln & 3) * 2;
        float s0 = g1[d0] * rsqrtf(v1[d0] + 1e-5f);
        float s1 = g1[d1] * rsqrtf(v1[d1] + 1e-5f);
        uint4 b;
        b.x = pack_bf16x2(W1[d0 * H0C + k] * s0,     W1[d0 * H0C + k + 1] * s0);
        b.y = pack_bf16x2(W1[d0 * H0C + k + 8] * s0, W1[d0 * H0C + k + 9] * s0);
        b.z = pack_bf16x2(W1[d1 * H0C + k] * s1,     W1[d1 * H0C + k + 1] * s1);
        b.w = pack_bf16x2(W1[d1 * H0C + k + 8] * s1, W1[d1 * H0C + k + 9] * s1);
        W1F4[idx] = b;
    }
    for (int c = tid; c < H0C; c += THREADS) {
        float s = g0[c] * rsqrtf(v0[c] + 1e-5f);
        bn0S[c] = b0[c] - m0[c] * s;
    }
    for (int d = tid; d < H1C; d += THREADS) {
        float s = g1[d] * rsqrtf(v1[d] + 1e-5f);
        bn1S[d] = b1[d] - m1[d] * s;
        woutS[d] = Wout[d];
    }
    if (tid == 0) boutS[0] = bout[0];
    __syncthreads();
    const float boutv = boutS[0];

    // warp roles: 4 m-groups (wm) x 6 n-groups (wn)
    const int wm = wid & 3;
    const int wn = wid >> 2;

    // buildX constants
    const int bx_kt  = lane >> 2;
    const int bx_pl0 = (2 * lane) & 7;
    const int bx_w0  = (bx_pl0 & 3) * 4;
    const int bx_ph0 = (bx_pl0 >> 2) * 2;
    const int bx_w1  = ((bx_pl0 + 1) & 3) * 4;
    const int bx_ph1 = ((bx_pl0 + 1) >> 2) * 2;

    for (int t = blockIdx.x; t < TILES_SYM; t += GRIDX) {
        // ---- map t -> (i, jb) over the upper-triangle tile set ----
        int ib = (t >= 1024) + (t >= 1920) + (t >= 2688) + (t >= 3328)
               + (t >= 3840) + (t >= 4224) + (t >= 4480);
        int base = 128 * (8 * ib - (ib * (ib - 1)) / 2);
        const int local = t - base;
        const int njb   = 8 - ib;
        const int idiv  = local / njb;
        const int i     = ib * 128 + idiv;
        const int jb    = ib + (local - idiv * njb);

        // ---------- buildX: GROUP-LOCAL rows p = wm*32 + wn + 6*rr ----------
        {
            const float4 fi4 = ((const float4*)(feat + i * FF))[lane];
#pragma unroll
            for (int rr = 0; rr < 6; ++rr) {
                int pl = wn + 6 * rr;
                if (pl < 32) {
                    int p = wm * 32 + pl;
                    float4 fj4 = ((const float4*)(feat + (jb * 128 + p) * FF))[lane];
                    float x0 = fabsf(fi4.x - fj4.x);
                    float x1 = fabsf(fi4.y - fj4.y);
                    float x2 = fabsf(fi4.z - fj4.z);
                    float x3 = fabsf(fi4.w - fj4.w);
                    uint32_t wA = pack_bf16x2(x0, x1);
                    uint32_t wB = pack_bf16x2(x2, x3);
                    int mt = p >> 4, r16 = p & 15;
                    int gg = r16 & 7, rowbit = r16 >> 3;
                    int bidx = ((mt * 8 + bx_kt) * 33 + gg * 4) * 4;
                    Xw[bidx + bx_w0 + bx_ph0 + rowbit] = wA;
                    Xw[bidx + bx_w1 + bx_ph1 + rowbit] = wB;
                }
            }
        }
        group_bar(wm);   // XF[wm rows] built by this group only

        // ---------- GEMM1: [32 rows x 192] slice of X * W0'^T ----------
        float c1r[2][4][4];
#pragma unroll
        for (int mt = 0; mt < 2; ++mt)
#pragma unroll
            for (int nt = 0; nt < 4; ++nt)
#pragma unroll
                for (int r = 0; r < 4; ++r) c1r[mt][nt][r] = 0.0f;

#pragma unroll
        for (int kt = 0; kt < 8; ++kt) {
            uint4 a[2];
#pragma unroll
            for (int mt = 0; mt < 2; ++mt)
                a[mt] = XF4[((wm * 2 + mt) * 8 + kt) * 33 + lane];
#pragma unroll
            for (int q = 0; q < 2; ++q) {
                uint4 b = W0F4[((wn * 2 + q) * 8 + kt) * 32 + lane];
#pragma unroll
                for (int mt = 0; mt < 2; ++mt) {
                    mma_bf16(c1r[mt][q * 2 + 0], (const uint32_t*)&a[mt], b.x, b.y);
                    mma_bf16(c1r[mt][q * 2 + 1], (const uint32_t*)&a[mt], b.z, b.w);
                }
            }
        }

        // ---------- epilogue1: BN shift + leaky -> HF[wm rows] ----------
#pragma unroll
        for (int mt = 0; mt < 2; ++mt) {
            int mtg = wm * 2 + mt;
#pragma unroll
            for (int q = 0; q < 2; ++q) {
                int colA = wn * 32 + q * 16 + 2 * t4;
                int colB = colA + 8;
                float sA0 = bn0S[colA], sA1 = bn0S[colA + 1];
                float sB0 = bn0S[colB], sB1 = bn0S[colB + 1];
                uint4 val;
                val.x = pack_bf16x2(leaky(c1r[mt][q * 2][0] + sA0),
                                    leaky(c1r[mt][q * 2][1] + sA1));
                val.y = pack_bf16x2(leaky(c1r[mt][q * 2][2] + sA0),
                                    leaky(c1r[mt][q * 2][3] + sA1));
                val.z = pack_bf16x2(leaky(c1r[mt][q * 2 + 1][0] + sB0),
                                    leaky(c1r[mt][q * 2 + 1][1] + sB1));
                val.w = pack_bf16x2(leaky(c1r[mt][q * 2 + 1][2] + sB0),
                                    leaky(c1r[mt][q * 2 + 1][3] + sB1));
                HF4[(mtg * 12 + wn * 2 + q) * 32 + lane] = val;
            }
        }
        group_bar(wm);   // HF[wm rows] complete (written by this group only)

        // ---------- GEMM2: [32 rows x 96] = H[wm rows] * W1'^T ----------
        float c2r[2][2][4];
#pragma unroll
        for (int mt = 0; mt < 2; ++mt)
#pragma unroll
            for (int nt = 0; nt < 2; ++nt)
#pragma unroll
                for (int r = 0; r < 4; ++r) c2r[mt][nt][r] = 0.0f;

#pragma unroll
        for (int kt = 0; kt < 12; ++kt) {
            uint4 a[2];
#pragma unroll
            for (int mt = 0; mt < 2; ++mt)
                a[mt] = HF4[((wm * 2 + mt) * 12 + kt) * 32 + lane];
            uint4 b = W1F4[(wn * 12 + kt) * 32 + lane];
#pragma unroll
            for (int mt = 0; mt < 2; ++mt) {
                mma_bf16(c2r[mt][0], (const uint32_t*)&a[mt], b.x, b.y);
                mma_bf16(c2r[mt][1], (const uint32_t*)&a[mt], b.z, b.w);
            }
        }

        // ---------- epilogue2: BN shift + leaky + Wout dot + reduce ----------
#pragma unroll
        for (int mt = 0; mt < 2; ++mt) {
#pragma unroll
            for (int half = 0; half < 2; ++half) {
                float acc = 0.0f;
#pragma unroll
                for (int nt = 0; nt < 2; ++nt) {
                    int col0 = wn * 16 + nt * 8 + 2 * t4;
                    float h0 = leaky(c2r[mt][nt][half * 2 + 0] + bn1S[col0]);
                    float h1 = leaky(c2r[mt][nt][half * 2 + 1] + bn1S[col0 + 1]);
                    acc += woutS[col0] * h0 + woutS[col0 + 1] * h1;
                }
                acc += __shfl_xor_sync(0xffffffffu, acc, 1);
                acc += __shfl_xor_sync(0xffffffffu, acc, 2);
                if (t4 == 0) {
                    int row = (wm * 2 + mt) * 16 + half * 8 + g;
                    redS[wn * 128 + row] = acc;   // row in [wm*32, wm*32+32)
                }
            }
        }
        group_bar(wm);   // redS rows of this wm written only by this group

        // final logit/store: warp `wm` of wn==0 handles rows wm*32..+31
        if (wn == 0) {
            int row = wm * 32 + lane;
            float logit = redS[row] + redS[128 + row] + redS[256 + row]
                        + redS[384 + row] + redS[512 + row] + redS[640 + row]
                        + boutv;
            float s = 1.0f / (1.0f + __expf(-logit));
            int jcol = jb * 128 + row;
            sim_out[i * NN + jcol] = s;
            sim_out[jcol * NN + i] = s;   // symmetric mirror
        }
        // next tile's redS writes by group wm are ordered after this read via
        // this group's next two group_bars (reader warp participates in both)
    }
}

// ---- pass 2: partial column sums of sim over 128-row slabs (float4) ----
__device__ float g_colpart[8][NN];

__global__ void colsum_kernel(const float* __restrict__ sim) {
    int j4 = (blockIdx.x * 256 + threadIdx.x);   // gridDim.x = 1
    int slab = blockIdx.y;
    if (j4 < 256) {
        float4 s = make_float4(0.f, 0.f, 0.f, 0.f);
        int ibase = slab * 128;
#pragma unroll 4
        for (int i = 0; i < 128; ++i) {
            float4 v = ((const float4*)(sim + (ibase + i) * NN))[j4];
            s.x += v.x; s.y += v.y; s.z += v.z; s.w += v.w;
        }
        ((float4*)g_colpart[slab])[j4] = s;
    }
}

// ---- pass 3: edge = (sim + eye + 1e-6) / colsum_over_i (float4) ----
__global__ void edge_kernel(const float* __restrict__ sim, float* __restrict__ edge) {
    int idx4 = blockIdx.x * 256 + threadIdx.x;   // over float4 elements
    int i  = idx4 >> 8;                          // 256 float4 per row
    int j0 = (idx4 & 255) * 4;
    float4 den = make_float4(1.0f + NN * 1e-6f, 1.0f + NN * 1e-6f,
                             1.0f + NN * 1e-6f, 1.0f + NN * 1e-6f);
#pragma unroll
    for (int r = 0; r < 8; ++r) {
        float4 c = ((const float4*)g_colpart[r])[idx4 & 255];
        den.x += c.x; den.y += c.y; den.z += c.z; den.w += c.w;
    }
    float4 v = ((const float4*)sim)[idx4];
    v.x += ((i == j0 + 0) ? 1.0f : 0.0f) + 1e-6f;
    v.y += ((i == j0 + 1) ? 1.0f : 0.0f) + 1e-6f;
    v.z += ((i == j0 + 2) ? 1.0f : 0.0f) + 1e-6f;
    v.w += ((i == j0 + 3) ? 1.0f : 0.0f) + 1e-6f;
    v.x /= den.x; v.y /= den.y; v.z /= den.z; v.w /= den.w;
    ((float4*)edge)[idx4] = v;
}

extern "C" void kernel_launch(void* const* d_in, const int* in_sizes, int n_in,
                              void* d_out, int out_size) {
    const float* feat = (const float*)d_in[0];
    const float* W0   = (const float*)d_in[1];
    const float* g0   = (const float*)d_in[2];
    const float* b0   = (const float*)d_in[3];
    const float* m0   = (const float*)d_in[4];
    const float* v0   = (const float*)d_in[5];
    const float* W1   = (const float*)d_in[6];
    const float* g1   = (const float*)d_in[7];
    const float* b1   = (const float*)d_in[8];
    const float* m1   = (const float*)d_in[9];
    const float* v1   = (const float*)d_in[10];
    const float* Wout = (const float*)d_in[11];
    const float* bout = (const float*)d_in[12];

    float* out  = (float*)d_out;
    float* edge = out;              // edge_feat [1,N,N] first
    float* sim  = out + NN * NN;    // sim_val [N,N] second

    cudaFuncSetAttribute(edgenet_bf16_kernel,
                         cudaFuncAttributeMaxDynamicSharedMemorySize, SMEM_BYTES);

    edgenet_bf16_kernel<<<GRIDX, THREADS, SMEM_BYTES>>>(
        feat, W0, g0, b0, m0, v0, W1, g1, b1, m1, v1, Wout, bout, sim);

    colsum_kernel<<<dim3(1, 8), 256>>>(sim);
    edge_kernel<<<(NN * NN / 4) / 256, 256>>>(sim, edge);
}

// round 14
// speedup vs baseline: 1.0050x; 1.0016x over previous
#include <cuda_runtime.h>
#include <math.h>
#include <cstdint>

#define NN 1024
#define FF 128
#define H0C 192
#define H1C 96
#define THREADS 768
#define GRIDX 148
#define TILES_SYM 4608       // sum over ib of 128*(8-ib)

// ---------------- SMEM layout (bytes) ----------------
#define SM_W0F   0           // 12 qg * 8 kt * 32 * 16B = 49152
#define SM_W1F   49152       // 6 qg * 12 kt * 32 * 16B = 36864
#define SM_XF    86016       // 8 mt * 8 kt frags, 33-uint4 stride = 33792
#define SM_HF    119808      // 8 mt * 12 kt * 32 * 16B = 49152
#define SM_BN0   168960      // 192 floats
#define SM_BN1   169728      // 96 floats
#define SM_WOUT  170112      // 96 floats
#define SM_RED   170496      // 6*128 floats = 3072
#define SM_BOUT  173568
#define SMEM_BYTES 173584

__device__ __forceinline__ uint32_t pack_bf16x2(float lo, float hi) {
    uint32_t r;
    asm("cvt.rn.bf16x2.f32 %0, %1, %2;" : "=r"(r) : "f"(hi), "f"(lo));
    return r;
}
__device__ __forceinline__ float leaky(float x) {
    return fmaxf(x, 0.0f) + 0.01f * fminf(x, 0.0f);
}
__device__ __forceinline__ void mma_bf16(float* d, const uint32_t* a,
                                         uint32_t b0, uint32_t b1) {
    asm volatile(
        "mma.sync.aligned.m16n8k16.row.col.f32.bf16.bf16.f32 "
        "{%0,%1,%2,%3}, {%4,%5,%6,%7}, {%8,%9}, {%0,%1,%2,%3};"
        : "+f"(d[0]), "+f"(d[1]), "+f"(d[2]), "+f"(d[3])
        : "r"(a[0]), "r"(a[1]), "r"(a[2]), "r"(a[3]), "r"(b0), "r"(b1));
}
// group-scoped named barrier: 6 warps (192 threads) of wm-group
__device__ __forceinline__ void group_bar(int wm) {
    asm volatile("bar.sync %0, %1;" :: "r"(1 + wm), "r"(192) : "memory");
}

__global__ void __launch_bounds__(THREADS, 1) edgenet_bf16_kernel(
    const float* __restrict__ feat,
    const float* __restrict__ W0, const float* __restrict__ g0,
    const float* __restrict__ b0, const float* __restrict__ m0,
    const float* __restrict__ v0,
    const float* __restrict__ W1, const float* __restrict__ g1,
    const float* __restrict__ b1, const float* __restrict__ m1,
    const float* __restrict__ v1,
    const float* __restrict__ Wout, const float* __restrict__ bout,
    float* __restrict__ sim_out)
{
    extern __shared__ char smem[];
    uint4*    W0F4 = (uint4*)(smem + SM_W0F);
    uint4*    W1F4 = (uint4*)(smem + SM_W1F);
    uint4*    XF4  = (uint4*)(smem + SM_XF);
    uint32_t* Xw   = (uint32_t*)(smem + SM_XF);
    uint4*    HF4  = (uint4*)(smem + SM_HF);
    float*    bn0S = (float*)(smem + SM_BN0);
    float*    bn1S = (float*)(smem + SM_BN1);
    float*    woutS= (float*)(smem + SM_WOUT);
    float*    redS = (float*)(smem + SM_RED);
    float*    boutS= (float*)(smem + SM_BOUT);

    const int tid  = threadIdx.x;
    const int wid  = tid >> 5;
    const int lane = tid & 31;
    const int g    = lane >> 2;
    const int t4   = lane & 3;

    // ---- stage weights ONCE as bf16 B-fragments (BN scale folded) ----
    for (int idx = tid; idx < 12 * 8 * 32; idx += THREADS) {
        int qg = idx >> 8, kt = (idx >> 5) & 7, ln = idx & 31;
        int c0 = qg * 16 + (ln >> 2);
        int c1 = c0 + 8;
        int f  = kt * 16 + (ln & 3) * 2;
        float s0 = g0[c0] * rsqrtf(v0[c0] + 1e-5f);
        float s1 = g0[c1] * rsqrtf(v0[c1] + 1e-5f);
        uint4 b;
        b.x = pack_bf16x2(W0[c0 * FF + f] * s0,     W0[c0 * FF + f + 1] * s0);
        b.y = pack_bf16x2(W0[c0 * FF + f + 8] * s0, W0[c0 * FF + f + 9] * s0);
        b.z = pack_bf16x2(W0[c1 * FF + f] * s1,     W0[c1 * FF + f + 1] * s1);
        b.w = pack_bf16x2(W0[c1 * FF + f + 8] * s1, W0[c1 * FF + f + 9] * s1);
        W0F4[idx] = b;
    }
    for (int idx = tid; idx < 6 * 12 * 32; idx += THREADS) {
        int qg = idx / 384, kt = (idx / 32) % 12, ln = idx & 31;
        int d0 = qg * 16 + (ln >> 2);
        int d1 = d0 + 8;
        int k  = kt * 16 + (ln & 3) * 2;
        float s0 = g1[d0] * rsqrtf(v1[d0] + 1e-5f);
        float s1 = g1[d1] * rsqrtf(v1[d1] + 1e-5f);
        uint4 b;
        b.x = pack_bf16x2(W1[d0 * H0C + k] * s0,     W1[d0 * H0C + k + 1] * s0);
        b.y = pack_bf16x2(W1[d0 * H0C + k + 8] * s0, W1[d0 * H0C + k + 9] * s0);
        b.z = pack_bf16x2(W1[d1 * H0C + k] * s1,     W1[d1 * H0C + k + 1] * s1);
        b.w = pack_bf16x2(W1[d1 * H0C + k + 8] * s1, W1[d1 * H0C + k + 9] * s1);
        W1F4[idx] = b;
    }
    for (int c = tid; c < H0C; c += THREADS) {
        float s = g0[c] * rsqrtf(v0[c] + 1e-5f);
        bn0S[c] = b0[c] - m0[c] * s;
    }
    for (int d = tid; d < H1C; d += THREADS) {
        float s = g1[d] * rsqrtf(v1[d] + 1e-5f);
        bn1S[d] = b1[d] - m1[d] * s;
        woutS[d] = Wout[d];
    }
    if (tid == 0) boutS[0] = bout[0];
    __syncthreads();
    const float boutv = boutS[0];

    // warp roles: 4 m-groups (wm) x 6 n-groups (wn)
    const int wm = wid & 3;
    const int wn = wid >> 2;

    // buildX constants
    const int bx_kt  = lane >> 2;
    const int bx_pl0 = (2 * lane) & 7;
    const int bx_w0  = (bx_pl0 & 3) * 4;
    const int bx_ph0 = (bx_pl0 >> 2) * 2;
    const int bx_w1  = ((bx_pl0 + 1) & 3) * 4;
    const int bx_ph1 = ((bx_pl0 + 1) >> 2) * 2;

    for (int t = blockIdx.x; t < TILES_SYM; t += GRIDX) {
        // ---- map t -> (i, jb) over the upper-triangle tile set ----
        int ib = (t >= 1024) + (t >= 1920) + (t >= 2688) + (t >= 3328)
               + (t >= 3840) + (t >= 4224) + (t >= 4480);
        int base = 128 * (8 * ib - (ib * (ib - 1)) / 2);
        const int local = t - base;
        const int njb   = 8 - ib;
        const int idiv  = local / njb;
        const int i     = ib * 128 + idiv;
        const int jb    = ib + (local - idiv * njb);

        // ---------- buildX: GROUP-LOCAL rows p = wm*32 + wn + 6*rr ----------
        {
            const float4 fi4 = ((const float4*)(feat + i * FF))[lane];
#pragma unroll
            for (int rr = 0; rr < 6; ++rr) {
                int pl = wn + 6 * rr;
                if (pl < 32) {
                    int p = wm * 32 + pl;
                    float4 fj4 = ((const float4*)(feat + (jb * 128 + p) * FF))[lane];
                    float x0 = fabsf(fi4.x - fj4.x);
                    float x1 = fabsf(fi4.y - fj4.y);
                    float x2 = fabsf(fi4.z - fj4.z);
                    float x3 = fabsf(fi4.w - fj4.w);
                    uint32_t wA = pack_bf16x2(x0, x1);
                    uint32_t wB = pack_bf16x2(x2, x3);
                    int mt = p >> 4, r16 = p & 15;
                    int gg = r16 & 7, rowbit = r16 >> 3;
                    int bidx = ((mt * 8 + bx_kt) * 33 + gg * 4) * 4;
                    Xw[bidx + bx_w0 + bx_ph0 + rowbit] = wA;
                    Xw[bidx + bx_w1 + bx_ph1 + rowbit] = wB;
                }
            }
        }
        group_bar(wm);   // XF[wm rows] built by this group only

        // ---------- GEMM1: [32 rows x 192] slice of X * W0'^T ----------
        float c1r[2][4][4];
#pragma unroll
        for (int mt = 0; mt < 2; ++mt)
#pragma unroll
            for (int nt = 0; nt < 4; ++nt)
#pragma unroll
                for (int r = 0; r < 4; ++r) c1r[mt][nt][r] = 0.0f;

#pragma unroll
        for (int kt = 0; kt < 8; ++kt) {
            uint4 a[2];
#pragma unroll
            for (int mt = 0; mt < 2; ++mt)
                a[mt] = XF4[((wm * 2 + mt) * 8 + kt) * 33 + lane];
#pragma unroll
            for (int q = 0; q < 2; ++q) {
                uint4 b = W0F4[((wn * 2 + q) * 8 + kt) * 32 + lane];
#pragma unroll
                for (int mt = 0; mt < 2; ++mt) {
                    mma_bf16(c1r[mt][q * 2 + 0], (const uint32_t*)&a[mt], b.x, b.y);
                    mma_bf16(c1r[mt][q * 2 + 1], (const uint32_t*)&a[mt], b.z, b.w);
                }
            }
        }

        // ---------- epilogue1: BN shift + leaky -> HF[wm rows] ----------
#pragma unroll
        for (int mt = 0; mt < 2; ++mt) {
            int mtg = wm * 2 + mt;
#pragma unroll
            for (int q = 0; q < 2; ++q) {
                int colA = wn * 32 + q * 16 + 2 * t4;
                int colB = colA + 8;
                float sA0 = bn0S[colA], sA1 = bn0S[colA + 1];
                float sB0 = bn0S[colB], sB1 = bn0S[colB + 1];
                uint4 val;
                val.x = pack_bf16x2(leaky(c1r[mt][q * 2][0] + sA0),
                                    leaky(c1r[mt][q * 2][1] + sA1));
                val.y = pack_bf16x2(leaky(c1r[mt][q * 2][2] + sA0),
                                    leaky(c1r[mt][q * 2][3] + sA1));
                val.z = pack_bf16x2(leaky(c1r[mt][q * 2 + 1][0] + sB0),
                                    leaky(c1r[mt][q * 2 + 1][1] + sB1));
                val.w = pack_bf16x2(leaky(c1r[mt][q * 2 + 1][2] + sB0),
                                    leaky(c1r[mt][q * 2 + 1][3] + sB1));
                HF4[(mtg * 12 + wn * 2 + q) * 32 + lane] = val;
            }
        }
        group_bar(wm);   // HF[wm rows] complete (written by this group only)

        // ---------- GEMM2: [32 rows x 96] = H[wm rows] * W1'^T ----------
        float c2r[2][2][4];
#pragma unroll
        for (int mt = 0; mt < 2; ++mt)
#pragma unroll
            for (int nt = 0; nt < 2; ++nt)
#pragma unroll
                for (int r = 0; r < 4; ++r) c2r[mt][nt][r] = 0.0f;

#pragma unroll
        for (int kt = 0; kt < 12; ++kt) {
            uint4 a[2];
#pragma unroll
            for (int mt = 0; mt < 2; ++mt)
                a[mt] = HF4[((wm * 2 + mt) * 12 + kt) * 32 + lane];
            uint4 b = W1F4[(wn * 12 + kt) * 32 + lane];
#pragma unroll
            for (int mt = 0; mt < 2; ++mt) {
                mma_bf16(c2r[mt][0], (const uint32_t*)&a[mt], b.x, b.y);
                mma_bf16(c2r[mt][1], (const uint32_t*)&a[mt], b.z, b.w);
            }
        }

        // ---------- epilogue2: BN shift + leaky + Wout dot + reduce ----------
#pragma unroll
        for (int mt = 0; mt < 2; ++mt) {
#pragma unroll
            for (int half = 0; half < 2; ++half) {
                float acc = 0.0f;
#pragma unroll
                for (int nt = 0; nt < 2; ++nt) {
                    int col0 = wn * 16 + nt * 8 + 2 * t4;
                    float h0 = leaky(c2r[mt][nt][half * 2 + 0] + bn1S[col0]);
                    float h1 = leaky(c2r[mt][nt][half * 2 + 1] + bn1S[col0 + 1]);
                    acc += woutS[col0] * h0 + woutS[col0 + 1] * h1;
                }
                acc += __shfl_xor_sync(0xffffffffu, acc, 1);
                acc += __shfl_xor_sync(0xffffffffu, acc, 2);
                if (t4 == 0) {
                    int row = (wm * 2 + mt) * 16 + half * 8 + g;
                    redS[wn * 128 + row] = acc;   // row in [wm*32, wm*32+32)
                }
            }
        }
        group_bar(wm);   // redS rows of this wm written only by this group

        // final logit/store: warp `wm` of wn==0 handles rows wm*32..+31
        if (wn == 0) {
            int row = wm * 32 + lane;
            float logit = redS[row] + redS[128 + row] + redS[256 + row]
                        + redS[384 + row] + redS[512 + row] + redS[640 + row]
                        + boutv;
            float s = 1.0f / (1.0f + __expf(-logit));
            int jcol = jb * 128 + row;
            sim_out[i * NN + jcol] = s;
            sim_out[jcol * NN + i] = s;   // symmetric mirror
        }
        // next tile's redS writes by group wm are ordered after this read via
        // this group's next two group_bars (reader warp participates in both)
    }
}

// ---- pass 2: partial column sums of sim over 128-row slabs (float4) ----
__device__ float g_colpart[8][NN];

__global__ void colsum_kernel(const float* __restrict__ sim) {
    int j4 = (blockIdx.x * 256 + threadIdx.x);   // gridDim.x = 1
    int slab = blockIdx.y;
    if (j4 < 256) {
        float4 s = make_float4(0.f, 0.f, 0.f, 0.f);
        int ibase = slab * 128;
#pragma unroll 4
        for (int i = 0; i < 128; ++i) {
            float4 v = ((const float4*)(sim + (ibase + i) * NN))[j4];
            s.x += v.x; s.y += v.y; s.z += v.z; s.w += v.w;
        }
        ((float4*)g_colpart[slab])[j4] = s;
    }
}

// ---- pass 3: edge = (sim + eye + 1e-6) / colsum_over_i (float4) ----
__global__ void edge_kernel(const float* __restrict__ sim, float* __restrict__ edge) {
    int idx4 = blockIdx.x * 256 + threadIdx.x;   // over float4 elements
    int i  = idx4 >> 8;                          // 256 float4 per row
    int j0 = (idx4 & 255) * 4;
    float4 den = make_float4(1.0f + NN * 1e-6f, 1.0f + NN * 1e-6f,
                             1.0f + NN * 1e-6f, 1.0f + NN * 1e-6f);
#pragma unroll
    for (int r = 0; r < 8; ++r) {
        float4 c = ((const float4*)g_colpart[r])[idx4 & 255];
        den.x += c.x; den.y += c.y; den.z += c.z; den.w += c.w;
    }
    float4 v = ((const float4*)sim)[idx4];
    v.x += ((i == j0 + 0) ? 1.0f : 0.0f) + 1e-6f;
    v.y += ((i == j0 + 1) ? 1.0f : 0.0f) + 1e-6f;
    v.z += ((i == j0 + 2) ? 1.0f : 0.0f) + 1e-6f;
    v.w += ((i == j0 + 3) ? 1.0f : 0.0f) + 1e-6f;
    v.x /= den.x; v.y /= den.y; v.z /= den.z; v.w /= den.w;
    ((float4*)edge)[idx4] = v;
}

extern "C" void kernel_launch(void* const* d_in, const int* in_sizes, int n_in,
                              void* d_out, int out_size) {
    const float* feat = (const float*)d_in[0];
    const float* W0   = (const float*)d_in[1];
    const float* g0   = (const float*)d_in[2];
    const float* b0   = (const float*)d_in[3];
    const float* m0   = (const float*)d_in[4];
    const float* v0   = (const float*)d_in[5];
    const float* W1   = (const float*)d_in[6];
    const float* g1   = (const float*)d_in[7];
    const float* b1   = (const float*)d_in[8];
    const float* m1   = (const float*)d_in[9];
    const float* v1   = (const float*)d_in[10];
    const float* Wout = (const float*)d_in[11];
    const float* bout = (const float*)d_in[12];

    float* out  = (float*)d_out;
    float* edge = out;              // edge_feat [1,N,N] first
    float* sim  = out + NN * NN;    // sim_val [N,N] second

    cudaFuncSetAttribute(edgenet_bf16_kernel,
                         cudaFuncAttributeMaxDynamicSharedMemorySize, SMEM_BYTES);

    edgenet_bf16_kernel<<<GRIDX, THREADS, SMEM_BYTES>>>(
        feat, W0, g0, b0, m0, v0, W1, g1, b1, m1, v1, Wout, bout, sim);

    colsum_kernel<<<dim3(1, 8), 256>>>(sim);
    edge_kernel<<<(NN * NN / 4) / 256, 256>>>(sim, edge);
}

// round 15
// speedup vs baseline: 1.0117x; 1.0067x over previous
#include <cuda_runtime.h>
#include <math.h>
#include <cstdint>

#define NN 1024
#define FF 128
#define H0C 192
#define H1C 96
#define THREADS 768
#define GRIDX 148
#define TILES_SYM 4608       // sum over ib of 128*(8-ib)

// ---------------- SMEM layout (bytes) ----------------
#define SM_W0F   0           // 12 qg * 8 kt * 32 * 16B = 49152
#define SM_W1F   49152       // 6 qg * 12 kt * 32 * 16B = 36864
#define SM_XF    86016       // 8 mt * 8 kt frags, 33-uint4 stride = 33792
#define SM_HF    119808      // 8 mt * 12 kt * 32 * 16B = 49152
#define SM_BN0   168960      // 192 floats
#define SM_BN1   169728      // 96 floats
#define SM_WOUT  170112      // 96 floats
#define SM_RED   170496      // 6*128 floats = 3072
#define SM_BOUT  173568
#define SMEM_BYTES 173584

__device__ __forceinline__ uint32_t pack_bf16x2(float lo, float hi) {
    uint32_t r;
    asm("cvt.rn.bf16x2.f32 %0, %1, %2;" : "=r"(r) : "f"(hi), "f"(lo));
    return r;
}
__device__ __forceinline__ float leaky(float x) {
    return fmaxf(x, 0.0f) + 0.01f * fminf(x, 0.0f);
}
__device__ __forceinline__ void mma_bf16(float* d, const uint32_t* a,
                                         uint32_t b0, uint32_t b1) {
    asm volatile(
        "mma.sync.aligned.m16n8k16.row.col.f32.bf16.bf16.f32 "
        "{%0,%1,%2,%3}, {%4,%5,%6,%7}, {%8,%9}, {%0,%1,%2,%3};"
        : "+f"(d[0]), "+f"(d[1]), "+f"(d[2]), "+f"(d[3])
        : "r"(a[0]), "r"(a[1]), "r"(a[2]), "r"(a[3]), "r"(b0), "r"(b1));
}
// group-scoped named barrier: 6 warps (192 threads) of wm-group
__device__ __forceinline__ void group_bar(int wm) {
    asm volatile("bar.sync %0, %1;" :: "r"(1 + wm), "r"(192) : "memory");
}

__global__ void __launch_bounds__(THREADS, 1) edgenet_bf16_kernel(
    const float* __restrict__ feat,
    const float* __restrict__ W0, const float* __restrict__ g0,
    const float* __restrict__ b0, const float* __restrict__ m0,
    const float* __restrict__ v0,
    const float* __restrict__ W1, const float* __restrict__ g1,
    const float* __restrict__ b1, const float* __restrict__ m1,
    const float* __restrict__ v1,
    const float* __restrict__ Wout, const float* __restrict__ bout,
    float* __restrict__ sim_out)
{
    extern __shared__ char smem[];
    uint4*    W0F4 = (uint4*)(smem + SM_W0F);
    uint4*    W1F4 = (uint4*)(smem + SM_W1F);
    uint4*    XF4  = (uint4*)(smem + SM_XF);
    uint32_t* Xw   = (uint32_t*)(smem + SM_XF);
    uint4*    HF4  = (uint4*)(smem + SM_HF);
    float*    bn0S = (float*)(smem + SM_BN0);
    float*    bn1S = (float*)(smem + SM_BN1);
    float*    woutS= (float*)(smem + SM_WOUT);
    float*    redS = (float*)(smem + SM_RED);
    float*    boutS= (float*)(smem + SM_BOUT);

    const int tid  = threadIdx.x;
    const int wid  = tid >> 5;
    const int lane = tid & 31;
    const int g    = lane >> 2;
    const int t4   = lane & 3;

    // ---- stage weights ONCE as bf16 B-fragments (BN scale folded) ----
    for (int idx = tid; idx < 12 * 8 * 32; idx += THREADS) {
        int qg = idx >> 8, kt = (idx >> 5) & 7, ln = idx & 31;
        int c0 = qg * 16 + (ln >> 2);
        int c1 = c0 + 8;
        int f  = kt * 16 + (ln & 3) * 2;
        float s0 = g0[c0] * rsqrtf(v0[c0] + 1e-5f);
        float s1 = g0[c1] * rsqrtf(v0[c1] + 1e-5f);
        uint4 b;
        b.x = pack_bf16x2(W0[c0 * FF + f] * s0,     W0[c0 * FF + f + 1] * s0);
        b.y = pack_bf16x2(W0[c0 * FF + f + 8] * s0, W0[c0 * FF + f + 9] * s0);
        b.z = pack_bf16x2(W0[c1 * FF + f] * s1,     W0[c1 * FF + f + 1] * s1);
        b.w = pack_bf16x2(W0[c1 * FF + f + 8] * s1, W0[c1 * FF + f + 9] * s1);
        W0F4[idx] = b;
    }
    for (int idx = tid; idx < 6 * 12 * 32; idx += THREADS) {
        int qg = idx / 384, kt = (idx / 32) % 12, ln = idx & 31;
        int d0 = qg * 16 + (ln >> 2);
        int d1 = d0 + 8;
        int k  = kt * 16 + (ln & 3) * 2;
        float s0 = g1[d0] * rsqrtf(v1[d0] + 1e-5f);
        float s1 = g1[d1] * rsqrtf(v1[d1] + 1e-5f);
        uint4 b;
        b.x = pack_bf16x2(W1[d0 * H0C + k] * s0,     W1[d0 * H0C + k + 1] * s0);
        b.y = pack_bf16x2(W1[d0 * H0C + k + 8] * s0, W1[d0 * H0C + k + 9] * s0);
        b.z = pack_bf16x2(W1[d1 * H0C + k] * s1,     W1[d1 * H0C + k + 1] * s1);
        b.w = pack_bf16x2(W1[d1 * H0C + k + 8] * s1, W1[d1 * H0C + k + 9] * s1);
        W1F4[idx] = b;
    }
    for (int c = tid; c < H0C; c += THREADS) {
        float s = g0[c] * rsqrtf(v0[c] + 1e-5f);
        bn0S[c] = b0[c] - m0[c] * s;
    }
    for (int d = tid; d < H1C; d += THREADS) {
        float s = g1[d] * rsqrtf(v1[d] + 1e-5f);
        bn1S[d] = b1[d] - m1[d] * s;
        woutS[d] = Wout[d];
    }
    if (tid == 0) boutS[0] = bout[0];
    __syncthreads();
    const float boutv = boutS[0];

    // warp roles: 4 m-groups (wm) x 6 n-groups (wn)
    const int wm = wid & 3;
    const int wn = wid >> 2;

    // buildX constants
    const int bx_kt  = lane >> 2;
    const int bx_pl0 = (2 * lane) & 7;
    const int bx_w0  = (bx_pl0 & 3) * 4;
    const int bx_ph0 = (bx_pl0 >> 2) * 2;
    const int bx_w1  = ((bx_pl0 + 1) & 3) * 4;
    const int bx_ph1 = ((bx_pl0 + 1) >> 2) * 2;

    for (int t = blockIdx.x; t < TILES_SYM; t += GRIDX) {
        // ---- map t -> (i, jb) over the upper-triangle tile set ----
        int ib = (t >= 1024) + (t >= 1920) + (t >= 2688) + (t >= 3328)
               + (t >= 3840) + (t >= 4224) + (t >= 4480);
        int base = 128 * (8 * ib - (ib * (ib - 1)) / 2);
        const int local = t - base;
        const int njb   = 8 - ib;
        const int idiv  = local / njb;
        const int i     = ib * 128 + idiv;
        const int jb    = ib + (local - idiv * njb);

        // ---------- buildX: GROUP-LOCAL rows p = wm*32 + wn + 6*rr ----------
        {
            const float4 fi4 = ((const float4*)(feat + i * FF))[lane];
#pragma unroll
            for (int rr = 0; rr < 6; ++rr) {
                int pl = wn + 6 * rr;
                if (pl < 32) {
                    int p = wm * 32 + pl;
                    float4 fj4 = ((const float4*)(feat + (jb * 128 + p) * FF))[lane];
                    float x0 = fabsf(fi4.x - fj4.x);
                    float x1 = fabsf(fi4.y - fj4.y);
                    float x2 = fabsf(fi4.z - fj4.z);
                    float x3 = fabsf(fi4.w - fj4.w);
                    uint32_t wA = pack_bf16x2(x0, x1);
                    uint32_t wB = pack_bf16x2(x2, x3);
                    int mt = p >> 4, r16 = p & 15;
                    int gg = r16 & 7, rowbit = r16 >> 3;
                    int bidx = ((mt * 8 + bx_kt) * 33 + gg * 4) * 4;
                    Xw[bidx + bx_w0 + bx_ph0 + rowbit] = wA;
                    Xw[bidx + bx_w1 + bx_ph1 + rowbit] = wB;
                }
            }
        }
        group_bar(wm);   // XF[wm rows] built by this group only

        // ---------- GEMM1: [32 rows x 192] slice of X * W0'^T ----------
        float c1r[2][4][4];
#pragma unroll
        for (int mt = 0; mt < 2; ++mt)
#pragma unroll
            for (int nt = 0; nt < 4; ++nt)
#pragma unroll
                for (int r = 0; r < 4; ++r) c1r[mt][nt][r] = 0.0f;

#pragma unroll
        for (int kt = 0; kt < 8; ++kt) {
            uint4 a[2];
#pragma unroll
            for (int mt = 0; mt < 2; ++mt)
                a[mt] = XF4[((wm * 2 + mt) * 8 + kt) * 33 + lane];
#pragma unroll
            for (int q = 0; q < 2; ++q) {
                uint4 b = W0F4[((wn * 2 + q) * 8 + kt) * 32 + lane];
#pragma unroll
                for (int mt = 0; mt < 2; ++mt) {
                    mma_bf16(c1r[mt][q * 2 + 0], (const uint32_t*)&a[mt], b.x, b.y);
                    mma_bf16(c1r[mt][q * 2 + 1], (const uint32_t*)&a[mt], b.z, b.w);
                }
            }
        }

        // ---------- epilogue1: BN shift + leaky -> HF[wm rows] ----------
#pragma unroll
        for (int mt = 0; mt < 2; ++mt) {
            int mtg = wm * 2 + mt;
#pragma unroll
            for (int q = 0; q < 2; ++q) {
                int colA = wn * 32 + q * 16 + 2 * t4;
                int colB = colA + 8;
                float sA0 = bn0S[colA], sA1 = bn0S[colA + 1];
                float sB0 = bn0S[colB], sB1 = bn0S[colB + 1];
                uint4 val;
                val.x = pack_bf16x2(leaky(c1r[mt][q * 2][0] + sA0),
                                    leaky(c1r[mt][q * 2][1] + sA1));
                val.y = pack_bf16x2(leaky(c1r[mt][q * 2][2] + sA0),
                                    leaky(c1r[mt][q * 2][3] + sA1));
                val.z = pack_bf16x2(leaky(c1r[mt][q * 2 + 1][0] + sB0),
                                    leaky(c1r[mt][q * 2 + 1][1] + sB1));
                val.w = pack_bf16x2(leaky(c1r[mt][q * 2 + 1][2] + sB0),
                                    leaky(c1r[mt][q * 2 + 1][3] + sB1));
                HF4[(mtg * 12 + wn * 2 + q) * 32 + lane] = val;
            }
        }
        group_bar(wm);   // HF[wm rows] complete (written by this group only)

        // ---------- GEMM2: [32 rows x 96] = H[wm rows] * W1'^T ----------
        float c2r[2][2][4];
#pragma unroll
        for (int mt = 0; mt < 2; ++mt)
#pragma unroll
            for (int nt = 0; nt < 2; ++nt)
#pragma unroll
                for (int r = 0; r < 4; ++r) c2r[mt][nt][r] = 0.0f;

#pragma unroll
        for (int kt = 0; kt < 12; ++kt) {
            uint4 a[2];
#pragma unroll
            for (int mt = 0; mt < 2; ++mt)
                a[mt] = HF4[((wm * 2 + mt) * 12 + kt) * 32 + lane];
            uint4 b = W1F4[(wn * 12 + kt) * 32 + lane];
#pragma unroll
            for (int mt = 0; mt < 2; ++mt) {
                mma_bf16(c2r[mt][0], (const uint32_t*)&a[mt], b.x, b.y);
                mma_bf16(c2r[mt][1], (const uint32_t*)&a[mt], b.z, b.w);
            }
        }

        // ---------- epilogue2: BN shift + leaky + Wout dot + reduce ----------
#pragma unroll
        for (int mt = 0; mt < 2; ++mt) {
#pragma unroll
            for (int half = 0; half < 2; ++half) {
                float acc = 0.0f;
#pragma unroll
                for (int nt = 0; nt < 2; ++nt) {
                    int col0 = wn * 16 + nt * 8 + 2 * t4;
                    float h0 = leaky(c2r[mt][nt][half * 2 + 0] + bn1S[col0]);
                    float h1 = leaky(c2r[mt][nt][half * 2 + 1] + bn1S[col0 + 1]);
                    acc += woutS[col0] * h0 + woutS[col0 + 1] * h1;
                }
                acc += __shfl_xor_sync(0xffffffffu, acc, 1);
                acc += __shfl_xor_sync(0xffffffffu, acc, 2);
                if (t4 == 0) {
                    int row = (wm * 2 + mt) * 16 + half * 8 + g;
                    redS[wn * 128 + row] = acc;   // row in [wm*32, wm*32+32)
                }
            }
        }
        group_bar(wm);   // redS rows of this wm written only by this group

        // final logit/store: warp `wm` of wn==0 handles rows wm*32..+31
        if (wn == 0) {
            int row = wm * 32 + lane;
            float logit = redS[row] + redS[128 + row] + redS[256 + row]
                        + redS[384 + row] + redS[512 + row] + redS[640 + row]
                        + boutv;
            float s = 1.0f / (1.0f + __expf(-logit));
            int jcol = jb * 128 + row;
            sim_out[i * NN + jcol] = s;
            sim_out[jcol * NN + i] = s;   // symmetric mirror
        }
        // next tile's redS writes by group wm are ordered after this read via
        // this group's next two group_bars (reader warp participates in both)
    }
}

// ---- pass 2: partial column sums of sim over 128-row slabs (float4) ----
__device__ float g_colpart[8][NN];

__global__ void colsum_kernel(const float* __restrict__ sim) {
    int j4 = (blockIdx.x * 256 + threadIdx.x);   // gridDim.x = 1
    int slab = blockIdx.y;
    if (j4 < 256) {
        float4 s = make_float4(0.f, 0.f, 0.f, 0.f);
        int ibase = slab * 128;
#pragma unroll 4
        for (int i = 0; i < 128; ++i) {
            float4 v = ((const float4*)(sim + (ibase + i) * NN))[j4];
            s.x += v.x; s.y += v.y; s.z += v.z; s.w += v.w;
        }
        ((float4*)g_colpart[slab])[j4] = s;
    }
}

// ---- pass 3: edge = (sim + eye + 1e-6) / colsum_over_i (float4) ----
__global__ void edge_kernel(const float* __restrict__ sim, float* __restrict__ edge) {
    int idx4 = blockIdx.x * 256 + threadIdx.x;   // over float4 elements
    int i  = idx4 >> 8;                          // 256 float4 per row
    int j0 = (idx4 & 255) * 4;
    float4 den = make_float4(1.0f + NN * 1e-6f, 1.0f + NN * 1e-6f,
                             1.0f + NN * 1e-6f, 1.0f + NN * 1e-6f);
#pragma unroll
    for (int r = 0; r < 8; ++r) {
        float4 c = ((const float4*)g_colpart[r])[idx4 & 255];
        den.x += c.x; den.y += c.y; den.z += c.z; den.w += c.w;
    }
    float4 v = ((const float4*)sim)[idx4];
    v.x += ((i == j0 + 0) ? 1.0f : 0.0f) + 1e-6f;
    v.y += ((i == j0 + 1) ? 1.0f : 0.0f) + 1e-6f;
    v.z += ((i == j0 + 2) ? 1.0f : 0.0f) + 1e-6f;
    v.w += ((i == j0 + 3) ? 1.0f : 0.0f) + 1e-6f;
    v.x /= den.x; v.y /= den.y; v.z /= den.z; v.w /= den.w;
    ((float4*)edge)[idx4] = v;
}

extern "C" void kernel_launch(void* const* d_in, const int* in_sizes, int n_in,
                              void* d_out, int out_size) {
    const float* feat = (const float*)d_in[0];
    const float* W0   = (const float*)d_in[1];
    const float* g0   = (const float*)d_in[2];
    const float* b0   = (const float*)d_in[3];
    const float* m0   = (const float*)d_in[4];
    const float* v0   = (const float*)d_in[5];
    const float* W1   = (const float*)d_in[6];
    const float* g1   = (const float*)d_in[7];
    const float* b1   = (const float*)d_in[8];
    const float* m1   = (const float*)d_in[9];
    const float* v1   = (const float*)d_in[10];
    const float* Wout = (const float*)d_in[11];
    const float* bout = (const float*)d_in[12];

    float* out  = (float*)d_out;
    float* edge = out;              // edge_feat [1,N,N] first
    float* sim  = out + NN * NN;    // sim_val [N,N] second

    cudaFuncSetAttribute(edgenet_bf16_kernel,
                         cudaFuncAttributeMaxDynamicSharedMemorySize, SMEM_BYTES);

    edgenet_bf16_kernel<<<GRIDX, THREADS, SMEM_BYTES>>>(
        feat, W0, g0, b0, m0, v0, W1, g1, b1, m1, v1, Wout, bout, sim);

    colsum_kernel<<<dim3(1, 8), 256>>>(sim);
    edge_kernel<<<(NN * NN / 4) / 256, 256>>>(sim, edge);
}

// round 16
// speedup vs baseline: 1.0119x; 1.0002x over previous
#include <cuda_runtime.h>
#include <math.h>
#include <cstdint>

#define NN 1024
#define FF 128
#define H0C 192
#define H1C 96
#define THREADS 768
#define GRIDX 148
#define TILES_SYM 4608       // sum over ib of 128*(8-ib)

// ---------------- SMEM layout (bytes) ----------------
#define SM_W0F   0           // 12 qg * 8 kt * 32 * 16B = 49152
#define SM_W1F   49152       // 6 qg * 12 kt * 32 * 16B = 36864
#define SM_XF    86016       // 8 mt * 8 kt frags, 33-uint4 stride = 33792
#define SM_HF    119808      // 8 mt * 12 kt * 32 * 16B = 49152
#define SM_BN0   168960      // 192 floats
#define SM_BN1   169728      // 96 floats
#define SM_WOUT  170112      // 96 floats
#define SM_RED   170496      // 6*128 floats = 3072
#define SM_BOUT  173568
#define SMEM_BYTES 173584

__device__ __forceinline__ uint32_t pack_bf16x2(float lo, float hi) {
    uint32_t r;
    asm("cvt.rn.bf16x2.f32 %0, %1, %2;" : "=r"(r) : "f"(hi), "f"(lo));
    return r;
}
__device__ __forceinline__ float leaky(float x) {
    return fmaxf(x, 0.0f) + 0.01f * fminf(x, 0.0f);
}
__device__ __forceinline__ void mma_bf16(float* d, const uint32_t* a,
                                         uint32_t b0, uint32_t b1) {
    asm volatile(
        "mma.sync.aligned.m16n8k16.row.col.f32.bf16.bf16.f32 "
        "{%0,%1,%2,%3}, {%4,%5,%6,%7}, {%8,%9}, {%0,%1,%2,%3};"
        : "+f"(d[0]), "+f"(d[1]), "+f"(d[2]), "+f"(d[3])
        : "r"(a[0]), "r"(a[1]), "r"(a[2]), "r"(a[3]), "r"(b0), "r"(b1));
}
// group-scoped named barrier: 6 warps (192 threads) of wm-group
__device__ __forceinline__ void group_bar(int wm) {
    asm volatile("bar.sync %0, %1;" :: "r"(1 + wm), "r"(192) : "memory");
}

__global__ void __launch_bounds__(THREADS, 1) edgenet_bf16_kernel(
    const float* __restrict__ feat,
    const float* __restrict__ W0, const float* __restrict__ g0,
    const float* __restrict__ b0, const float* __restrict__ m0,
    const float* __restrict__ v0,
    const float* __restrict__ W1, const float* __restrict__ g1,
    const float* __restrict__ b1, const float* __restrict__ m1,
    const float* __restrict__ v1,
    const float* __restrict__ Wout, const float* __restrict__ bout,
    float* __restrict__ sim_out)
{
    extern __shared__ char smem[];
    uint4*    W0F4 = (uint4*)(smem + SM_W0F);
    uint4*    W1F4 = (uint4*)(smem + SM_W1F);
    uint4*    XF4  = (uint4*)(smem + SM_XF);
    uint32_t* Xw   = (uint32_t*)(smem + SM_XF);
    uint4*    HF4  = (uint4*)(smem + SM_HF);
    float*    bn0S = (float*)(smem + SM_BN0);
    float*    bn1S = (float*)(smem + SM_BN1);
    float*    woutS= (float*)(smem + SM_WOUT);
    float*    redS = (float*)(smem + SM_RED);
    float*    boutS= (float*)(smem + SM_BOUT);

    const int tid  = threadIdx.x;
    const int wid  = tid >> 5;
    const int lane = tid & 31;
    const int g    = lane >> 2;
    const int t4   = lane & 3;

    // ---- stage weights ONCE as bf16 B-fragments (BN scale folded) ----
    for (int idx = tid; idx < 12 * 8 * 32; idx += THREADS) {
        int qg = idx >> 8, kt = (idx >> 5) & 7, ln = idx & 31;
        int c0 = qg * 16 + (ln >> 2);
        int c1 = c0 + 8;
        int f  = kt * 16 + (ln & 3) * 2;
        float s0 = g0[c0] * rsqrtf(v0[c0] + 1e-5f);
        float s1 = g0[c1] * rsqrtf(v0[c1] + 1e-5f);
        uint4 b;
        b.x = pack_bf16x2(W0[c0 * FF + f] * s0,     W0[c0 * FF + f + 1] * s0);
        b.y = pack_bf16x2(W0[c0 * FF + f + 8] * s0, W0[c0 * FF + f + 9] * s0);
        b.z = pack_bf16x2(W0[c1 * FF + f] * s1,     W0[c1 * FF + f + 1] * s1);
        b.w = pack_bf16x2(W0[c1 * FF + f + 8] * s1, W0[c1 * FF + f + 9] * s1);
        W0F4[idx] = b;
    }
    for (int idx = tid; idx < 6 * 12 * 32; idx += THREADS) {
        int qg = idx / 384, kt = (idx / 32) % 12, ln = idx & 31;
        int d0 = qg * 16 + (ln >> 2);
        int d1 = d0 + 8;
        int k  = kt * 16 + (ln & 3) * 2;
        float s0 = g1[d0] * rsqrtf(v1[d0] + 1e-5f);
        float s1 = g1[d1] * rsqrtf(v1[d1] + 1e-5f);
        uint4 b;
        b.x = pack_bf16x2(W1[d0 * H0C + k] * s0,     W1[d0 * H0C + k + 1] * s0);
        b.y = pack_bf16x2(W1[d0 * H0C + k + 8] * s0, W1[d0 * H0C + k + 9] * s0);
        b.z = pack_bf16x2(W1[d1 * H0C + k] * s1,     W1[d1 * H0C + k + 1] * s1);
        b.w = pack_bf16x2(W1[d1 * H0C + k + 8] * s1, W1[d1 * H0C + k + 9] * s1);
        W1F4[idx] = b;
    }
    for (int c = tid; c < H0C; c += THREADS) {
        float s = g0[c] * rsqrtf(v0[c] + 1e-5f);
        bn0S[c] = b0[c] - m0[c] * s;
    }
    for (int d = tid; d < H1C; d += THREADS) {
        float s = g1[d] * rsqrtf(v1[d] + 1e-5f);
        bn1S[d] = b1[d] - m1[d] * s;
        woutS[d] = Wout[d];
    }
    if (tid == 0) boutS[0] = bout[0];
    __syncthreads();
    const float boutv = boutS[0];

    // warp roles: 4 m-groups (wm) x 6 n-groups (wn)
    const int wm = wid & 3;
    const int wn = wid >> 2;

    // buildX constants
    const int bx_kt  = lane >> 2;
    const int bx_pl0 = (2 * lane) & 7;
    const int bx_w0  = (bx_pl0 & 3) * 4;
    const int bx_ph0 = (bx_pl0 >> 2) * 2;
    const int bx_w1  = ((bx_pl0 + 1) & 3) * 4;
    const int bx_ph1 = ((bx_pl0 + 1) >> 2) * 2;

    for (int t = blockIdx.x; t < TILES_SYM; t += GRIDX) {
        // ---- map t -> (i, jb) over the upper-triangle tile set ----
        int ib = (t >= 1024) + (t >= 1920) + (t >= 2688) + (t >= 3328)
               + (t >= 3840) + (t >= 4224) + (t >= 4480);
        int base = 128 * (8 * ib - (ib * (ib - 1)) / 2);
        const int local = t - base;
        const int njb   = 8 - ib;
        const int idiv  = local / njb;
        const int i     = ib * 128 + idiv;
        const int jb    = ib + (local - idiv * njb);

        // ---------- buildX: GROUP-LOCAL rows p = wm*32 + wn + 6*rr ----------
        {
            const float4 fi4 = ((const float4*)(feat + i * FF))[lane];
#pragma unroll
            for (int rr = 0; rr < 6; ++rr) {
                int pl = wn + 6 * rr;
                if (pl < 32) {
                    int p = wm * 32 + pl;
                    float4 fj4 = ((const float4*)(feat + (jb * 128 + p) * FF))[lane];
                    float x0 = fabsf(fi4.x - fj4.x);
                    float x1 = fabsf(fi4.y - fj4.y);
                    float x2 = fabsf(fi4.z - fj4.z);
                    float x3 = fabsf(fi4.w - fj4.w);
                    uint32_t wA = pack_bf16x2(x0, x1);
                    uint32_t wB = pack_bf16x2(x2, x3);
                    int mt = p >> 4, r16 = p & 15;
                    int gg = r16 & 7, rowbit = r16 >> 3;
                    int bidx = ((mt * 8 + bx_kt) * 33 + gg * 4) * 4;
                    Xw[bidx + bx_w0 + bx_ph0 + rowbit] = wA;
                    Xw[bidx + bx_w1 + bx_ph1 + rowbit] = wB;
                }
            }
        }
        group_bar(wm);   // XF[wm rows] built by this group only

        // ---------- GEMM1: [32 rows x 192] slice of X * W0'^T ----------
        float c1r[2][4][4];
#pragma unroll
        for (int mt = 0; mt < 2; ++mt)
#pragma unroll
            for (int nt = 0; nt < 4; ++nt)
#pragma unroll
                for (int r = 0; r < 4; ++r) c1r[mt][nt][r] = 0.0f;

#pragma unroll
        for (int kt = 0; kt < 8; ++kt) {
            uint4 a[2];
#pragma unroll
            for (int mt = 0; mt < 2; ++mt)
                a[mt] = XF4[((wm * 2 + mt) * 8 + kt) * 33 + lane];
#pragma unroll
            for (int q = 0; q < 2; ++q) {
                uint4 b = W0F4[((wn * 2 + q) * 8 + kt) * 32 + lane];
#pragma unroll
                for (int mt = 0; mt < 2; ++mt) {
                    mma_bf16(c1r[mt][q * 2 + 0], (const uint32_t*)&a[mt], b.x, b.y);
                    mma_bf16(c1r[mt][q * 2 + 1], (const uint32_t*)&a[mt], b.z, b.w);
                }
            }
        }

        // ---------- epilogue1: BN shift + leaky -> HF[wm rows] ----------
#pragma unroll
        for (int mt = 0; mt < 2; ++mt) {
            int mtg = wm * 2 + mt;
#pragma unroll
            for (int q = 0; q < 2; ++q) {
                int colA = wn * 32 + q * 16 + 2 * t4;
                int colB = colA + 8;
                float sA0 = bn0S[colA], sA1 = bn0S[colA + 1];
                float sB0 = bn0S[colB], sB1 = bn0S[colB + 1];
                uint4 val;
                val.x = pack_bf16x2(leaky(c1r[mt][q * 2][0] + sA0),
                                    leaky(c1r[mt][q * 2][1] + sA1));
                val.y = pack_bf16x2(leaky(c1r[mt][q * 2][2] + sA0),
                                    leaky(c1r[mt][q * 2][3] + sA1));
                val.z = pack_bf16x2(leaky(c1r[mt][q * 2 + 1][0] + sB0),
                                    leaky(c1r[mt][q * 2 + 1][1] + sB1));
                val.w = pack_bf16x2(leaky(c1r[mt][q * 2 + 1][2] + sB0),
                                    leaky(c1r[mt][q * 2 + 1][3] + sB1));
                HF4[(mtg * 12 + wn * 2 + q) * 32 + lane] = val;
            }
        }
        group_bar(wm);   // HF[wm rows] complete (written by this group only)

        // ---------- GEMM2: [32 rows x 96] = H[wm rows] * W1'^T ----------
        float c2r[2][2][4];
#pragma unroll
        for (int mt = 0; mt < 2; ++mt)
#pragma unroll
            for (int nt = 0; nt < 2; ++nt)
#pragma unroll
                for (int r = 0; r < 4; ++r) c2r[mt][nt][r] = 0.0f;

#pragma unroll
        for (int kt = 0; kt < 12; ++kt) {
            uint4 a[2];
#pragma unroll
            for (int mt = 0; mt < 2; ++mt)
                a[mt] = HF4[((wm * 2 + mt) * 12 + kt) * 32 + lane];
            uint4 b = W1F4[(wn * 12 + kt) * 32 + lane];
#pragma unroll
            for (int mt = 0; mt < 2; ++mt) {
                mma_bf16(c2r[mt][0], (const uint32_t*)&a[mt], b.x, b.y);
                mma_bf16(c2r[mt][1], (const uint32_t*)&a[mt], b.z, b.w);
            }
        }

        // ---------- epilogue2: BN shift + leaky + Wout dot + reduce ----------
#pragma unroll
        for (int mt = 0; mt < 2; ++mt) {
#pragma unroll
            for (int half = 0; half < 2; ++half) {
                float acc = 0.0f;
#pragma unroll
                for (int nt = 0; nt < 2; ++nt) {
                    int col0 = wn * 16 + nt * 8 + 2 * t4;
                    float h0 = leaky(c2r[mt][nt][half * 2 + 0] + bn1S[col0]);
                    float h1 = leaky(c2r[mt][nt][half * 2 + 1] + bn1S[col0 + 1]);
                    acc += woutS[col0] * h0 + woutS[col0 + 1] * h1;
                }
                acc += __shfl_xor_sync(0xffffffffu, acc, 1);
                acc += __shfl_xor_sync(0xffffffffu, acc, 2);
                if (t4 == 0) {
                    int row = (wm * 2 + mt) * 16 + half * 8 + g;
                    redS[wn * 128 + row] = acc;   // row in [wm*32, wm*32+32)
                }
            }
        }
        group_bar(wm);   // redS rows of this wm written only by this group

        // final logit/store: warp `wm` of wn==0 handles rows wm*32..+31
        if (wn == 0) {
            int row = wm * 32 + lane;
            float logit = redS[row] + redS[128 + row] + redS[256 + row]
                        + redS[384 + row] + redS[512 + row] + redS[640 + row]
                        + boutv;
            float s = 1.0f / (1.0f + __expf(-logit));
            int jcol = jb * 128 + row;
            sim_out[i * NN + jcol] = s;
            sim_out[jcol * NN + i] = s;   // symmetric mirror
        }
        // next tile's redS writes by group wm are ordered after this read via
        // this group's next two group_bars (reader warp participates in both)
    }
}

// ---- pass 2: partial column sums of sim over 128-row slabs (float4) ----
__device__ float g_colpart[8][NN];

__global__ void colsum_kernel(const float* __restrict__ sim) {
    int j4 = (blockIdx.x * 256 + threadIdx.x);   // gridDim.x = 1
    int slab = blockIdx.y;
    if (j4 < 256) {
        float4 s = make_float4(0.f, 0.f, 0.f, 0.f);
        int ibase = slab * 128;
#pragma unroll 4
        for (int i = 0; i < 128; ++i) {
            float4 v = ((const float4*)(sim + (ibase + i) * NN))[j4];
            s.x += v.x; s.y += v.y; s.z += v.z; s.w += v.w;
        }
        ((float4*)g_colpart[slab])[j4] = s;
    }
}

// ---- pass 3: edge = (sim + eye + 1e-6) / colsum_over_i (float4) ----
__global__ void edge_kernel(const float* __restrict__ sim, float* __restrict__ edge) {
    int idx4 = blockIdx.x * 256 + threadIdx.x;   // over float4 elements
    int i  = idx4 >> 8;                          // 256 float4 per row
    int j0 = (idx4 & 255) * 4;
    float4 den = make_float4(1.0f + NN * 1e-6f, 1.0f + NN * 1e-6f,
                             1.0f + NN * 1e-6f, 1.0f + NN * 1e-6f);
#pragma unroll
    for (int r = 0; r < 8; ++r) {
        float4 c = ((const float4*)g_colpart[r])[idx4 & 255];
        den.x += c.x; den.y += c.y; den.z += c.z; den.w += c.w;
    }
    float4 v = ((const float4*)sim)[idx4];
    v.x += ((i == j0 + 0) ? 1.0f : 0.0f) + 1e-6f;
    v.y += ((i == j0 + 1) ? 1.0f : 0.0f) + 1e-6f;
    v.z += ((i == j0 + 2) ? 1.0f : 0.0f) + 1e-6f;
    v.w += ((i == j0 + 3) ? 1.0f : 0.0f) + 1e-6f;
    v.x /= den.x; v.y /= den.y; v.z /= den.z; v.w /= den.w;
    ((float4*)edge)[idx4] = v;
}

extern "C" void kernel_launch(void* const* d_in, const int* in_sizes, int n_in,
                              void* d_out, int out_size) {
    const float* feat = (const float*)d_in[0];
    const float* W0   = (const float*)d_in[1];
    const float* g0   = (const float*)d_in[2];
    const float* b0   = (const float*)d_in[3];
    const float* m0   = (const float*)d_in[4];
    const float* v0   = (const float*)d_in[5];
    const float* W1   = (const float*)d_in[6];
    const float* g1   = (const float*)d_in[7];
    const float* b1   = (const float*)d_in[8];
    const float* m1   = (const float*)d_in[9];
    const float* v1   = (const float*)d_in[10];
    const float* Wout = (const float*)d_in[11];
    const float* bout = (const float*)d_in[12];

    float* out  = (float*)d_out;
    float* edge = out;              // edge_feat [1,N,N] first
    float* sim  = out + NN * NN;    // sim_val [N,N] second

    cudaFuncSetAttribute(edgenet_bf16_kernel,
                         cudaFuncAttributeMaxDynamicSharedMemorySize, SMEM_BYTES);

    edgenet_bf16_kernel<<<GRIDX, THREADS, SMEM_BYTES>>>(
        feat, W0, g0, b0, m0, v0, W1, g1, b1, m1, v1, Wout, bout, sim);

    colsum_kernel<<<dim3(1, 8), 256>>>(sim);
    edge_kernel<<<(NN * NN / 4) / 256, 256>>>(sim, edge);
}